// round 3
// baseline (speedup 1.0000x reference)
#include <cuda_runtime.h>

#define N_NODES 100000
#define N_EDGES 1600000
#define CC 64
#define NL 3
#define TILE 64
#define SCAN_BLK 1024
#define N_SCANB ((N_NODES + SCAN_BLK - 1) / SCAN_BLK)   // 98

// Static device scratch (allowed).
__device__ float g_xa[N_NODES * CC];
__device__ float g_xb[N_NODES * CC];
__device__ int   g_cnt[N_NODES];
__device__ int   g_off[N_NODES];
__device__ int   g_cur[N_NODES];
__device__ int   g_csr[N_EDGES];
__device__ int   g_bsum[N_SCANB + 1];

// ---------------- packed f32x2 helpers (Blackwell FFMA2) --------------------
__device__ __forceinline__ unsigned long long pk2(float a, float b) {
    unsigned long long r;
    asm("mov.b64 %0, {%1, %2};" : "=l"(r) : "f"(a), "f"(b));
    return r;
}
__device__ __forceinline__ void upk2(float& a, float& b, unsigned long long v) {
    asm("mov.b64 {%0, %1}, %2;" : "=f"(a), "=f"(b) : "l"(v));
}
__device__ __forceinline__ void fma2(unsigned long long& d,
                                     unsigned long long a, unsigned long long b) {
    asm("fma.rn.f32x2 %0, %1, %2, %0;" : "+l"(d) : "l"(a), "l"(b));
}

// ---------------- CSR build (once per launch) -------------------------------

__global__ void hist_kernel(const int* __restrict__ ei, int* __restrict__ cnt) {
    int e = blockIdx.x * blockDim.x + threadIdx.x;
    if (e < N_EDGES) atomicAdd(&cnt[ei[N_EDGES + e]], 1);
}

__global__ void scan_blocks_kernel(const int* __restrict__ cnt,
                                   int* __restrict__ off, int* __restrict__ bsum) {
    __shared__ int sm[SCAN_BLK];
    int gid = blockIdx.x * SCAN_BLK + threadIdx.x;
    int v = (gid < N_NODES) ? cnt[gid] : 0;
    sm[threadIdx.x] = v;
    __syncthreads();
    #pragma unroll
    for (int o = 1; o < SCAN_BLK; o <<= 1) {
        int t = (threadIdx.x >= o) ? sm[threadIdx.x - o] : 0;
        __syncthreads();
        sm[threadIdx.x] += t;
        __syncthreads();
    }
    if (gid < N_NODES) off[gid] = sm[threadIdx.x] - v;  // exclusive
    if (threadIdx.x == SCAN_BLK - 1) bsum[blockIdx.x] = sm[threadIdx.x];
}

// Parallel scan of 98 block sums (single 128-thread block).
__global__ void scan_bsum_kernel(int* __restrict__ bsum) {
    __shared__ int sm[128];
    int t = threadIdx.x;
    int v = (t < N_SCANB) ? bsum[t] : 0;
    sm[t] = v;
    __syncthreads();
    #pragma unroll
    for (int o = 1; o < 128; o <<= 1) {
        int u = (t >= o) ? sm[t - o] : 0;
        __syncthreads();
        sm[t] += u;
        __syncthreads();
    }
    if (t < N_SCANB) bsum[t] = sm[t] - v;  // exclusive
}

__global__ void add_off_kernel(int* __restrict__ off, const int* __restrict__ bsum,
                               int* __restrict__ cur) {
    int gid = blockIdx.x * blockDim.x + threadIdx.x;
    if (gid < N_NODES) {
        int v = off[gid] + bsum[gid / SCAN_BLK];
        off[gid] = v;
        cur[gid] = v;
    }
}

__global__ void fill_csr_kernel(const int* __restrict__ ei,
                                int* __restrict__ cur, int* __restrict__ csr) {
    int e = blockIdx.x * blockDim.x + threadIdx.x;
    if (e < N_EDGES) {
        int d = ei[N_EDGES + e];
        int p = atomicAdd(&cur[d], 1);
        csr[p] = ei[e];
    }
}

// ---------------- Fused GIN layer: gather + agg + MLP + BNs -----------------
// Block: 64-node tile, 256 threads. Phase A: 8 warps gather 8 nodes each into
// smem sH. Phase B/C: two 64x64 GEMMs with packed-f32x2 FMA (BN folded).

#define HP 66  // sH pitch (even -> aligned float2; 4*66 mod 32 banks spreads)

__global__ void __launch_bounds__(256, 4)
fused_layer_kernel(const float* __restrict__ x, const int* __restrict__ off,
                   const int* __restrict__ cnt, const int* __restrict__ csr,
                   const float* __restrict__ eps, int layer,
                   float* __restrict__ out,
                   const float* __restrict__ W1, const float* __restrict__ b1,
                   const float* __restrict__ g1, const float* __restrict__ be1,
                   const float* __restrict__ W2, const float* __restrict__ b2,
                   const float* __restrict__ g2, const float* __restrict__ be2,
                   const float* __restrict__ bng, const float* __restrict__ bnb,
                   int do_relu) {
    extern __shared__ float smem[];
    float* sW1 = smem;            // [64][64] BN1-folded
    float* sW2 = smem + 4096;     // [64][64] BN2-folded
    float* sH  = smem + 8192;     // [64][HP]
    const float bns = 0.999995000037f;  // 1/sqrt(1+1e-5)

    int tid  = threadIdx.x;
    int lane = tid & 31;
    int w    = tid >> 5;
    int rowbase = blockIdx.x * TILE;

    // Folded weight load (overlaps with gather via scoreboard).
    for (int idx = tid; idx < 4096; idx += 256) {
        int j = idx & 63;
        sW1[idx] = W1[idx] * (g1[j] * bns);
        sW2[idx] = W2[idx] * (g2[j] * bns);
    }

    // Phase A: gather/aggregate 8 nodes per warp directly into sH.
    float e = 1.0f + __ldg(&eps[layer]);
    for (int i = 0; i < 8; i++) {
        int r  = w * 8 + i;
        int gr = rowbase + r;
        float2 acc = make_float2(0.f, 0.f);
        if (gr < N_NODES) {
            int base = __ldg(&off[gr]);
            int deg  = __ldg(&cnt[gr]);
            for (int c = 0; c < deg; c += 32) {
                int rem = deg - c;
                int m = rem < 32 ? rem : 32;
                int myi = (lane < m) ? __ldg(&csr[base + c + lane]) : 0;
                for (int j = 0; j < m; j++) {
                    int s = __shfl_sync(0xffffffffu, myi, j);
                    float2 v = *(const float2*)(x + (size_t)s * CC + lane * 2);
                    acc.x += v.x; acc.y += v.y;
                }
            }
            float2 xv = *(const float2*)(x + (size_t)gr * CC + lane * 2);
            acc.x = fmaf(e, xv.x, acc.x);
            acc.y = fmaf(e, xv.y, acc.y);
        }
        *(float2*)&sH[r * HP + lane * 2] = acc;
    }
    __syncthreads();

    // Phase B: GEMM1 (h @ W1f + c1), packed f32x2.
    int tx = tid & 15, ty = tid >> 4;
    int jb = tx * 4;
    int rb = ty * 4;

    unsigned long long acc2[4][2];
    {
        float c0 = b1[jb + 0] * (g1[jb + 0] * bns) + be1[jb + 0];
        float c1 = b1[jb + 1] * (g1[jb + 1] * bns) + be1[jb + 1];
        float c2 = b1[jb + 2] * (g1[jb + 2] * bns) + be1[jb + 2];
        float c3 = b1[jb + 3] * (g1[jb + 3] * bns) + be1[jb + 3];
        unsigned long long p01 = pk2(c0, c1), p23 = pk2(c2, c3);
        #pragma unroll
        for (int r = 0; r < 4; r++) { acc2[r][0] = p01; acc2[r][1] = p23; }
    }
    #pragma unroll 4
    for (int k = 0; k < 64; k++) {
        unsigned long long b01 = *(const unsigned long long*)&sW1[k * 64 + jb];
        unsigned long long b23 = *(const unsigned long long*)&sW1[k * 64 + jb + 2];
        #pragma unroll
        for (int r = 0; r < 4; r++) {
            float a = sH[(rb + r) * HP + k];
            unsigned long long aa = pk2(a, a);
            fma2(acc2[r][0], aa, b01);
            fma2(acc2[r][1], aa, b23);
        }
    }
    __syncthreads();

    // ReLU, write h1 to sH.
    #pragma unroll
    for (int r = 0; r < 4; r++) {
        float v0, v1, v2, v3;
        upk2(v0, v1, acc2[r][0]);
        upk2(v2, v3, acc2[r][1]);
        float* p = &sH[(rb + r) * HP + jb];
        p[0] = fmaxf(v0, 0.f); p[1] = fmaxf(v1, 0.f);
        p[2] = fmaxf(v2, 0.f); p[3] = fmaxf(v3, 0.f);
    }
    __syncthreads();

    // Phase C: GEMM2.
    {
        float c0 = b2[jb + 0] * (g2[jb + 0] * bns) + be2[jb + 0];
        float c1 = b2[jb + 1] * (g2[jb + 1] * bns) + be2[jb + 1];
        float c2 = b2[jb + 2] * (g2[jb + 2] * bns) + be2[jb + 2];
        float c3 = b2[jb + 3] * (g2[jb + 3] * bns) + be2[jb + 3];
        unsigned long long p01 = pk2(c0, c1), p23 = pk2(c2, c3);
        #pragma unroll
        for (int r = 0; r < 4; r++) { acc2[r][0] = p01; acc2[r][1] = p23; }
    }
    #pragma unroll 4
    for (int k = 0; k < 64; k++) {
        unsigned long long b01 = *(const unsigned long long*)&sW2[k * 64 + jb];
        unsigned long long b23 = *(const unsigned long long*)&sW2[k * 64 + jb + 2];
        #pragma unroll
        for (int r = 0; r < 4; r++) {
            float a = sH[(rb + r) * HP + k];
            unsigned long long aa = pk2(a, a);
            fma2(acc2[r][0], aa, b01);
            fma2(acc2[r][1], aa, b23);
        }
    }

    // ReLU + outer BN (+ optional ReLU), store.
    float s0 = bng[jb + 0] * bns, s1 = bng[jb + 1] * bns;
    float s2 = bng[jb + 2] * bns, s3 = bng[jb + 3] * bns;
    float t0 = bnb[jb + 0], t1 = bnb[jb + 1];
    float t2 = bnb[jb + 2], t3 = bnb[jb + 3];
    #pragma unroll
    for (int r = 0; r < 4; r++) {
        int gr = rowbase + rb + r;
        if (gr >= N_NODES) continue;
        float v0, v1, v2, v3;
        upk2(v0, v1, acc2[r][0]);
        upk2(v2, v3, acc2[r][1]);
        float4 o;
        o.x = s0 * fmaxf(v0, 0.f) + t0;
        o.y = s1 * fmaxf(v1, 0.f) + t1;
        o.z = s2 * fmaxf(v2, 0.f) + t2;
        o.w = s3 * fmaxf(v3, 0.f) + t3;
        if (do_relu) {
            o.x = fmaxf(o.x, 0.f); o.y = fmaxf(o.y, 0.f);
            o.z = fmaxf(o.z, 0.f); o.w = fmaxf(o.w, 0.f);
        }
        *(float4*)(out + (size_t)gr * CC + jb) = o;
    }
}

extern "C" void kernel_launch(void* const* d_in, const int* in_sizes, int n_in,
                              void* d_out, int out_size) {
    const float* x   = (const float*)d_in[0];
    const int*   ei  = (const int*)d_in[1];
    const float* eps = (const float*)d_in[2];
    const float* W1  = (const float*)d_in[3];
    const float* b1  = (const float*)d_in[4];
    const float* g1  = (const float*)d_in[5];
    const float* be1 = (const float*)d_in[6];
    const float* W2  = (const float*)d_in[7];
    const float* b2  = (const float*)d_in[8];
    const float* g2  = (const float*)d_in[9];
    const float* be2 = (const float*)d_in[10];
    const float* bng = (const float*)d_in[11];
    const float* bnb = (const float*)d_in[12];
    float* out = (float*)d_out;

    float *xa, *xb;
    int *cnt, *off, *cur, *csr, *bsum;
    cudaGetSymbolAddress((void**)&xa,   g_xa);
    cudaGetSymbolAddress((void**)&xb,   g_xb);
    cudaGetSymbolAddress((void**)&cnt,  g_cnt);
    cudaGetSymbolAddress((void**)&off,  g_off);
    cudaGetSymbolAddress((void**)&cur,  g_cur);
    cudaGetSymbolAddress((void**)&csr,  g_csr);
    cudaGetSymbolAddress((void**)&bsum, g_bsum);

    const int smem_bytes = (8192 + TILE * HP) * 4;  // 49664
    cudaFuncSetAttribute(fused_layer_kernel,
                         cudaFuncAttributeMaxDynamicSharedMemorySize, smem_bytes);

    const int eblk = (N_EDGES + 255) / 256;
    const int nblk = (N_NODES + 255) / 256;
    const int fblk = (N_NODES + TILE - 1) / TILE;  // 1563

    // CSR build (edge_index constant across layers).
    cudaMemsetAsync(cnt, 0, N_NODES * sizeof(int));
    hist_kernel<<<eblk, 256>>>(ei, cnt);
    scan_blocks_kernel<<<N_SCANB, SCAN_BLK>>>(cnt, off, bsum);
    scan_bsum_kernel<<<1, 128>>>(bsum);
    add_off_kernel<<<nblk, 256>>>(off, bsum, cur);
    fill_csr_kernel<<<eblk, 256>>>(ei, cur, csr);

    const float* xin = x;
    float* outs[NL] = {xa, xb, out};
    for (int l = 0; l < NL; l++) {
        fused_layer_kernel<<<fblk, 256, smem_bytes>>>(
            xin, off, cnt, csr, eps, l, outs[l],
            W1 + l * 4096, b1 + l * 64, g1 + l * 64, be1 + l * 64,
            W2 + l * 4096, b2 + l * 64, g2 + l * 64, be2 + l * 64,
            bng + l * 64, bnb + l * 64, (l < NL - 1) ? 1 : 0);
        xin = outs[l];
    }
}

// round 5
// speedup vs baseline: 1.0981x; 1.0981x over previous
#include <cuda_runtime.h>

#define N_NODES 100000
#define N_EDGES 1600000
#define CC 64
#define NL 3
#define SCAN_BLK 1024
#define N_SCANB ((N_NODES + SCAN_BLK - 1) / SCAN_BLK)   // 98

// Static device scratch (allowed).
__device__ float g_h [N_NODES * CC];
__device__ float g_xa[N_NODES * CC];
__device__ float g_xb[N_NODES * CC];
__device__ int   g_cnt[N_NODES];
__device__ int   g_off[N_NODES];
__device__ int   g_cur[N_NODES];
__device__ int   g_csr[N_EDGES];
__device__ int   g_bsum[N_SCANB + 1];

// ---------------- packed f32x2 helpers (Blackwell FFMA2) --------------------
__device__ __forceinline__ unsigned long long pk2(float a, float b) {
    unsigned long long r;
    asm("mov.b64 %0, {%1, %2};" : "=l"(r) : "f"(a), "f"(b));
    return r;
}
__device__ __forceinline__ void upk2(float& a, float& b, unsigned long long v) {
    asm("mov.b64 {%0, %1}, %2;" : "=f"(a), "=f"(b) : "l"(v));
}
__device__ __forceinline__ void fma2(unsigned long long& d,
                                     unsigned long long a, unsigned long long b) {
    asm("fma.rn.f32x2 %0, %1, %2, %0;" : "+l"(d) : "l"(a), "l"(b));
}

// ---------------- CSR build (once per launch) -------------------------------

__global__ void hist_kernel(const int* __restrict__ ei, int* __restrict__ cnt) {
    int e = blockIdx.x * blockDim.x + threadIdx.x;
    if (e < N_EDGES) atomicAdd(&cnt[ei[N_EDGES + e]], 1);
}

__global__ void scan_blocks_kernel(const int* __restrict__ cnt,
                                   int* __restrict__ off, int* __restrict__ bsum) {
    __shared__ int sm[SCAN_BLK];
    int gid = blockIdx.x * SCAN_BLK + threadIdx.x;
    int v = (gid < N_NODES) ? cnt[gid] : 0;
    sm[threadIdx.x] = v;
    __syncthreads();
    #pragma unroll
    for (int o = 1; o < SCAN_BLK; o <<= 1) {
        int t = (threadIdx.x >= o) ? sm[threadIdx.x - o] : 0;
        __syncthreads();
        sm[threadIdx.x] += t;
        __syncthreads();
    }
    if (gid < N_NODES) off[gid] = sm[threadIdx.x] - v;  // exclusive
    if (threadIdx.x == SCAN_BLK - 1) bsum[blockIdx.x] = sm[threadIdx.x];
}

__global__ void scan_bsum_kernel(int* __restrict__ bsum) {
    __shared__ int sm[128];
    int t = threadIdx.x;
    int v = (t < N_SCANB) ? bsum[t] : 0;
    sm[t] = v;
    __syncthreads();
    #pragma unroll
    for (int o = 1; o < 128; o <<= 1) {
        int u = (t >= o) ? sm[t - o] : 0;
        __syncthreads();
        sm[t] += u;
        __syncthreads();
    }
    if (t < N_SCANB) bsum[t] = sm[t] - v;  // exclusive
}

__global__ void add_off_kernel(int* __restrict__ off, const int* __restrict__ bsum,
                               int* __restrict__ cur) {
    int gid = blockIdx.x * blockDim.x + threadIdx.x;
    if (gid < N_NODES) {
        int v = off[gid] + bsum[gid / SCAN_BLK];
        off[gid] = v;
        cur[gid] = v;
    }
}

__global__ void fill_csr_kernel(const int* __restrict__ ei,
                                int* __restrict__ cur, int* __restrict__ csr) {
    int e = blockIdx.x * blockDim.x + threadIdx.x;
    if (e < N_EDGES) {
        int d = ei[N_EDGES + e];
        int p = atomicAdd(&cur[d], 1);
        csr[p] = ei[e];
    }
}

// ---------------- Aggregation: warp-per-node, no atomics, no smem -----------
// h[n] = (1+eps)*x[n] + sum_{s in csr segment of n} x[s]
// (separate kernel: 64 warps/SM hide the random-L2 gather latency)

__global__ void __launch_bounds__(256)
agg_kernel(const float* __restrict__ x, const int* __restrict__ off,
           const int* __restrict__ cnt, const int* __restrict__ csr,
           const float* __restrict__ eps, int layer, float* __restrict__ h) {
    int warp = (blockIdx.x * blockDim.x + threadIdx.x) >> 5;
    int lane = threadIdx.x & 31;
    if (warp >= N_NODES) return;
    int base = off[warp];
    int deg  = cnt[warp];

    float2 acc = make_float2(0.f, 0.f);
    for (int c = 0; c < deg; c += 32) {
        int rem = deg - c;
        int m = rem < 32 ? rem : 32;
        int myi = (lane < m) ? __ldg(&csr[base + c + lane]) : 0;
        for (int j = 0; j < m; j++) {
            int s = __shfl_sync(0xffffffffu, myi, j);
            float2 v = *(const float2*)(x + (size_t)s * CC + lane * 2);
            acc.x += v.x; acc.y += v.y;
        }
    }
    float e = 1.0f + __ldg(&eps[layer]);
    float2 xv = *(const float2*)(x + (size_t)warp * CC + lane * 2);
    acc.x = fmaf(e, xv.x, acc.x);
    acc.y = fmaf(e, xv.y, acc.y);
    *(float2*)(h + (size_t)warp * CC + lane * 2) = acc;
}

// ---------------- Fused MLP (BN folded), packed-f32x2 mainloop --------------
// 128-row tiles, 256 threads; thread computes 8 rows x 4 cols.

__global__ void __launch_bounds__(256)
mlp_kernel(const float* __restrict__ h, float* __restrict__ out,
           const float* __restrict__ W1, const float* __restrict__ b1,
           const float* __restrict__ g1, const float* __restrict__ be1,
           const float* __restrict__ W2, const float* __restrict__ b2,
           const float* __restrict__ g2, const float* __restrict__ be2,
           const float* __restrict__ bng, const float* __restrict__ bnb,
           int do_relu) {
    extern __shared__ float smem[];
    float* sW1 = smem;                 // [64][64]
    float* sW2 = smem + 4096;          // [64][64]
    float* sH  = smem + 8192;          // [128][66]
    const int HP = 66;
    const float bns = 0.999995000037f; // 1/sqrt(1+1e-5)

    int tid = threadIdx.x;
    for (int idx = tid; idx < 4096; idx += 256) {
        int j = idx & 63;
        sW1[idx] = W1[idx] * (g1[j] * bns);
        sW2[idx] = W2[idx] * (g2[j] * bns);
    }
    int rowbase = blockIdx.x * 128;
    for (int idx = tid; idx < 128 * 16; idx += 256) {
        int r = idx >> 4, c4 = idx & 15;
        int gr = rowbase + r;
        float4 v = (gr < N_NODES) ? *(const float4*)(h + (size_t)gr * CC + c4 * 4)
                                  : make_float4(0.f, 0.f, 0.f, 0.f);
        float* p = &sH[r * HP + c4 * 4];
        p[0] = v.x; p[1] = v.y; p[2] = v.z; p[3] = v.w;
    }
    __syncthreads();

    int tx = tid & 15, ty = tid >> 4;
    int jb = tx * 4;
    int rb = ty * 8;

    unsigned long long acc2[8][2];

    // ---- GEMM 1 ----
    {
        float c0 = b1[jb + 0] * (g1[jb + 0] * bns) + be1[jb + 0];
        float c1 = b1[jb + 1] * (g1[jb + 1] * bns) + be1[jb + 1];
        float c2 = b1[jb + 2] * (g1[jb + 2] * bns) + be1[jb + 2];
        float c3 = b1[jb + 3] * (g1[jb + 3] * bns) + be1[jb + 3];
        unsigned long long p01 = pk2(c0, c1), p23 = pk2(c2, c3);
        #pragma unroll
        for (int r = 0; r < 8; r++) { acc2[r][0] = p01; acc2[r][1] = p23; }
    }
    #pragma unroll 4
    for (int k = 0; k < 64; k++) {
        unsigned long long b01 = *(const unsigned long long*)&sW1[k * 64 + jb];
        unsigned long long b23 = *(const unsigned long long*)&sW1[k * 64 + jb + 2];
        #pragma unroll
        for (int r = 0; r < 8; r++) {
            float a = sH[(rb + r) * HP + k];
            unsigned long long aa = pk2(a, a);
            fma2(acc2[r][0], aa, b01);
            fma2(acc2[r][1], aa, b23);
        }
    }
    __syncthreads();

    // ReLU -> sH
    #pragma unroll
    for (int r = 0; r < 8; r++) {
        float v0, v1, v2, v3;
        upk2(v0, v1, acc2[r][0]);
        upk2(v2, v3, acc2[r][1]);
        float* p = &sH[(rb + r) * HP + jb];
        p[0] = fmaxf(v0, 0.f); p[1] = fmaxf(v1, 0.f);
        p[2] = fmaxf(v2, 0.f); p[3] = fmaxf(v3, 0.f);
    }
    __syncthreads();

    // ---- GEMM 2 ----
    {
        float c0 = b2[jb + 0] * (g2[jb + 0] * bns) + be2[jb + 0];
        float c1 = b2[jb + 1] * (g2[jb + 1] * bns) + be2[jb + 1];
        float c2 = b2[jb + 2] * (g2[jb + 2] * bns) + be2[jb + 2];
        float c3 = b2[jb + 3] * (g2[jb + 3] * bns) + be2[jb + 3];
        unsigned long long p01 = pk2(c0, c1), p23 = pk2(c2, c3);
        #pragma unroll
        for (int r = 0; r < 8; r++) { acc2[r][0] = p01; acc2[r][1] = p23; }
    }
    #pragma unroll 4
    for (int k = 0; k < 64; k++) {
        unsigned long long b01 = *(const unsigned long long*)&sW2[k * 64 + jb];
        unsigned long long b23 = *(const unsigned long long*)&sW2[k * 64 + jb + 2];
        #pragma unroll
        for (int r = 0; r < 8; r++) {
            float a = sH[(rb + r) * HP + k];
            unsigned long long aa = pk2(a, a);
            fma2(acc2[r][0], aa, b01);
            fma2(acc2[r][1], aa, b23);
        }
    }

    // ReLU + outer BN (+ optional ReLU), store.
    float s0 = bng[jb + 0] * bns, s1 = bng[jb + 1] * bns;
    float s2 = bng[jb + 2] * bns, s3 = bng[jb + 3] * bns;
    float t0 = bnb[jb + 0], t1 = bnb[jb + 1];
    float t2 = bnb[jb + 2], t3 = bnb[jb + 3];
    #pragma unroll
    for (int r = 0; r < 8; r++) {
        int gr = rowbase + rb + r;
        if (gr >= N_NODES) continue;
        float v0, v1, v2, v3;
        upk2(v0, v1, acc2[r][0]);
        upk2(v2, v3, acc2[r][1]);
        float4 o;
        o.x = s0 * fmaxf(v0, 0.f) + t0;
        o.y = s1 * fmaxf(v1, 0.f) + t1;
        o.z = s2 * fmaxf(v2, 0.f) + t2;
        o.w = s3 * fmaxf(v3, 0.f) + t3;
        if (do_relu) {
            o.x = fmaxf(o.x, 0.f); o.y = fmaxf(o.y, 0.f);
            o.z = fmaxf(o.z, 0.f); o.w = fmaxf(o.w, 0.f);
        }
        *(float4*)(out + (size_t)gr * CC + jb) = o;
    }
}

extern "C" void kernel_launch(void* const* d_in, const int* in_sizes, int n_in,
                              void* d_out, int out_size) {
    const float* x   = (const float*)d_in[0];
    const int*   ei  = (const int*)d_in[1];
    const float* eps = (const float*)d_in[2];
    const float* W1  = (const float*)d_in[3];
    const float* b1  = (const float*)d_in[4];
    const float* g1  = (const float*)d_in[5];
    const float* be1 = (const float*)d_in[6];
    const float* W2  = (const float*)d_in[7];
    const float* b2  = (const float*)d_in[8];
    const float* g2  = (const float*)d_in[9];
    const float* be2 = (const float*)d_in[10];
    const float* bng = (const float*)d_in[11];
    const float* bnb = (const float*)d_in[12];
    float* out = (float*)d_out;

    float *hb, *xa, *xb;
    int *cnt, *off, *cur, *csr, *bsum;
    cudaGetSymbolAddress((void**)&hb,   g_h);
    cudaGetSymbolAddress((void**)&xa,   g_xa);
    cudaGetSymbolAddress((void**)&xb,   g_xb);
    cudaGetSymbolAddress((void**)&cnt,  g_cnt);
    cudaGetSymbolAddress((void**)&off,  g_off);
    cudaGetSymbolAddress((void**)&cur,  g_cur);
    cudaGetSymbolAddress((void**)&csr,  g_csr);
    cudaGetSymbolAddress((void**)&bsum, g_bsum);

    const int smem_bytes = (8192 + 128 * 66) * 4;  // 66560
    cudaFuncSetAttribute(mlp_kernel,
                         cudaFuncAttributeMaxDynamicSharedMemorySize, smem_bytes);

    const int eblk = (N_EDGES + 255) / 256;
    const int nblk = (N_NODES + 255) / 256;
    const int mlp_blocks = (N_NODES + 127) / 128;       // 782
    const int agg_blocks = (N_NODES * 32 + 255) / 256;  // 12500

    // CSR build (edge_index constant across layers).
    cudaMemsetAsync(cnt, 0, N_NODES * sizeof(int));
    hist_kernel<<<eblk, 256>>>(ei, cnt);
    scan_blocks_kernel<<<N_SCANB, SCAN_BLK>>>(cnt, off, bsum);
    scan_bsum_kernel<<<1, 128>>>(bsum);
    add_off_kernel<<<nblk, 256>>>(off, bsum, cur);
    fill_csr_kernel<<<eblk, 256>>>(ei, cur, csr);

    const float* xin = x;
    float* outs[NL] = {xa, xb, out};
    for (int l = 0; l < NL; l++) {
        agg_kernel<<<agg_blocks, 256>>>(xin, off, cnt, csr, eps, l, hb);
        mlp_kernel<<<mlp_blocks, 256, smem_bytes>>>(
            hb, outs[l],
            W1 + l * 4096, b1 + l * 64, g1 + l * 64, be1 + l * 64,
            W2 + l * 4096, b2 + l * 64, g2 + l * 64, be2 + l * 64,
            bng + l * 64, bnb + l * 64, (l < NL - 1) ? 1 : 0);
        xin = outs[l];
    }
}

// round 8
// speedup vs baseline: 1.3244x; 1.2061x over previous
#include <cuda_runtime.h>
#include <cstdint>

#define N_NODES 100000
#define N_EDGES 1600000
#define CC 64
#define NL 3
#define SCAN_BLK 1024
#define N_SCANB ((N_NODES + SCAN_BLK - 1) / SCAN_BLK)   // 98

// Static device scratch (allowed).
__device__ float g_h [N_NODES * CC];
__device__ float g_xa[N_NODES * CC];
__device__ float g_xb[N_NODES * CC];
__device__ int   g_cnt[N_NODES];
__device__ int   g_off[N_NODES];
__device__ int   g_cur[N_NODES];
__device__ int   g_csr[N_EDGES];
__device__ int   g_bsum[N_SCANB + 1];

// ---------------- tf32 mma helpers (sm_80+ baseline — no 'a' features) -----

__device__ __forceinline__ uint32_t f2tf32(float f) {
    uint32_t r;
    asm("cvt.rna.tf32.f32 %0, %1;" : "=r"(r) : "f"(f));
    return r;
}

__device__ __forceinline__ void mma_tf32(float* d,
                                         uint32_t a0, uint32_t a1,
                                         uint32_t a2, uint32_t a3,
                                         uint32_t b0, uint32_t b1) {
    asm volatile(
        "mma.sync.aligned.m16n8k8.row.col.f32.tf32.tf32.f32 "
        "{%0,%1,%2,%3}, {%4,%5,%6,%7}, {%8,%9}, {%0,%1,%2,%3};"
        : "+f"(d[0]), "+f"(d[1]), "+f"(d[2]), "+f"(d[3])
        : "r"(a0), "r"(a1), "r"(a2), "r"(a3), "r"(b0), "r"(b1));
}

// ---------------- CSR build (once per launch) -------------------------------

__global__ void hist_kernel(const int* __restrict__ ei, int* __restrict__ cnt) {
    int e = blockIdx.x * blockDim.x + threadIdx.x;
    if (e < N_EDGES) atomicAdd(&cnt[ei[N_EDGES + e]], 1);
}

__global__ void scan_blocks_kernel(const int* __restrict__ cnt,
                                   int* __restrict__ off, int* __restrict__ bsum) {
    __shared__ int sm[SCAN_BLK];
    int gid = blockIdx.x * SCAN_BLK + threadIdx.x;
    int v = (gid < N_NODES) ? cnt[gid] : 0;
    sm[threadIdx.x] = v;
    __syncthreads();
    #pragma unroll
    for (int o = 1; o < SCAN_BLK; o <<= 1) {
        int t = (threadIdx.x >= o) ? sm[threadIdx.x - o] : 0;
        __syncthreads();
        sm[threadIdx.x] += t;
        __syncthreads();
    }
    if (gid < N_NODES) off[gid] = sm[threadIdx.x] - v;
    if (threadIdx.x == SCAN_BLK - 1) bsum[blockIdx.x] = sm[threadIdx.x];
}

__global__ void scan_bsum_kernel(int* __restrict__ bsum) {
    __shared__ int sm[128];
    int t = threadIdx.x;
    int v = (t < N_SCANB) ? bsum[t] : 0;
    sm[t] = v;
    __syncthreads();
    #pragma unroll
    for (int o = 1; o < 128; o <<= 1) {
        int u = (t >= o) ? sm[t - o] : 0;
        __syncthreads();
        sm[t] += u;
        __syncthreads();
    }
    if (t < N_SCANB) bsum[t] = sm[t] - v;
}

__global__ void add_off_kernel(int* __restrict__ off, const int* __restrict__ bsum,
                               int* __restrict__ cur) {
    int gid = blockIdx.x * blockDim.x + threadIdx.x;
    if (gid < N_NODES) {
        int v = off[gid] + bsum[gid / SCAN_BLK];
        off[gid] = v;
        cur[gid] = v;
    }
}

__global__ void fill_csr_kernel(const int* __restrict__ ei,
                                int* __restrict__ cur, int* __restrict__ csr) {
    int e = blockIdx.x * blockDim.x + threadIdx.x;
    if (e < N_EDGES) {
        int d = ei[N_EDGES + e];
        int p = atomicAdd(&cur[d], 1);
        csr[p] = ei[e];
    }
}

// ---------------- Aggregation (unchanged, proven) ---------------------------

__global__ void __launch_bounds__(256)
agg_kernel(const float* __restrict__ x, const int* __restrict__ off,
           const int* __restrict__ cnt, const int* __restrict__ csr,
           const float* __restrict__ eps, int layer, float* __restrict__ h) {
    int warp = (blockIdx.x * blockDim.x + threadIdx.x) >> 5;
    int lane = threadIdx.x & 31;
    if (warp >= N_NODES) return;
    int base = off[warp];
    int deg  = cnt[warp];

    float2 acc = make_float2(0.f, 0.f);
    for (int c = 0; c < deg; c += 32) {
        int rem = deg - c;
        int m = rem < 32 ? rem : 32;
        int myi = (lane < m) ? __ldg(&csr[base + c + lane]) : 0;
        for (int j = 0; j < m; j++) {
            int s = __shfl_sync(0xffffffffu, myi, j);
            float2 v = *(const float2*)(x + (size_t)s * CC + lane * 2);
            acc.x += v.x; acc.y += v.y;
        }
    }
    float e = 1.0f + __ldg(&eps[layer]);
    float2 xv = *(const float2*)(x + (size_t)warp * CC + lane * 2);
    acc.x = fmaf(e, xv.x, acc.x);
    acc.y = fmaf(e, xv.y, acc.y);
    *(float2*)(h + (size_t)warp * CC + lane * 2) = acc;
}

// ---------------- MLP via mma.sync tf32 (HMMA) ------------------------------
// 256 threads = 8 warps; block tile = 128 rows x 64 cols, K = 64.
// Warp w owns rows w*16 .. w*16+15 and all 8 n-tiles (m16n8k8 fragments).
// A tile pitch 68 (conflict-free frag loads); W tiles [k][n] pitch 72
// (conflict-free b-frag loads). GEMM1->GEMM2 needs only __syncwarp().

#define AP 68
#define WP 72
// smem float offsets
#define SF_C1 0
#define SF_C2 64
#define SF_SG 128
#define SF_ST 192
#define SF_A  256                    // 128*68 = 8704
#define SF_W1 (SF_A + 128 * AP)      // 8960
#define SF_W2 (SF_W1 + 64 * WP)      // 13568
#define SF_TOT (SF_W2 + 64 * WP)     // 18176 floats = 72704 B

__global__ void __launch_bounds__(256)
mlp_tc_kernel(const float* __restrict__ h, float* __restrict__ out,
              const float* __restrict__ W1, const float* __restrict__ b1,
              const float* __restrict__ g1, const float* __restrict__ be1,
              const float* __restrict__ W2, const float* __restrict__ b2,
              const float* __restrict__ g2, const float* __restrict__ be2,
              const float* __restrict__ bng, const float* __restrict__ bnb,
              int do_relu) {
    extern __shared__ float smem[];
    float*    sc1 = smem + SF_C1;
    float*    sc2 = smem + SF_C2;
    float*    ssg = smem + SF_SG;
    float*    sst = smem + SF_ST;
    uint32_t* sA  = (uint32_t*)(smem + SF_A);
    uint32_t* sW1 = (uint32_t*)(smem + SF_W1);
    uint32_t* sW2 = (uint32_t*)(smem + SF_W2);
    const float bns = 0.999995000037f;  // 1/sqrt(1+1e-5)

    int tid = threadIdx.x;

    // Folded per-column constants.
    if (tid < 64) {
        sc1[tid] = b1[tid] * (g1[tid] * bns) + be1[tid];
        sc2[tid] = b2[tid] * (g2[tid] * bns) + be2[tid];
        ssg[tid] = bng[tid] * bns;
        sst[tid] = bnb[tid];
    }

    // BN-folded W tiles, [k][n], tf32-rounded.
    for (int idx = tid; idx < 4096; idx += 256) {
        int k = idx >> 6, n = idx & 63;
        sW1[k * WP + n] = f2tf32(W1[idx] * (g1[n] * bns));
        sW2[k * WP + n] = f2tf32(W2[idx] * (g2[n] * bns));
    }

    // A tile: h rows, tf32-rounded.
    int rowbase = blockIdx.x * 128;
    for (int idx = tid; idx < 2048; idx += 256) {
        int r = idx >> 4, k4 = idx & 15;
        int gr = rowbase + r;
        float4 v = (gr < N_NODES) ? *(const float4*)(h + (size_t)gr * CC + k4 * 4)
                                  : make_float4(0.f, 0.f, 0.f, 0.f);
        uint32_t* p = &sA[r * AP + k4 * 4];
        p[0] = f2tf32(v.x); p[1] = f2tf32(v.y);
        p[2] = f2tf32(v.z); p[3] = f2tf32(v.w);
    }
    __syncthreads();

    int lane = tid & 31, warp = tid >> 5;
    int g = lane >> 2, c = lane & 3;
    int rb = warp * 16;

    float acc[8][4];

    // ---- GEMM 1 ----
    #pragma unroll
    for (int nt = 0; nt < 8; nt++)
        #pragma unroll
        for (int i = 0; i < 4; i++) acc[nt][i] = 0.f;

    #pragma unroll
    for (int ks = 0; ks < 8; ks++) {
        int k0 = ks * 8;
        uint32_t a0 = sA[(rb + g)     * AP + k0 + c];
        uint32_t a1 = sA[(rb + g + 8) * AP + k0 + c];
        uint32_t a2 = sA[(rb + g)     * AP + k0 + c + 4];
        uint32_t a3 = sA[(rb + g + 8) * AP + k0 + c + 4];
        #pragma unroll
        for (int nt = 0; nt < 8; nt++) {
            uint32_t b0 = sW1[(k0 + c)     * WP + nt * 8 + g];
            uint32_t b1r = sW1[(k0 + c + 4) * WP + nt * 8 + g];
            mma_tf32(acc[nt], a0, a1, a2, a3, b0, b1r);
        }
    }

    // Epilogue 1: ReLU(z + c1) -> tf32 -> back into sA (warp-local rows).
    #pragma unroll
    for (int nt = 0; nt < 8; nt++) {
        int j0 = nt * 8 + 2 * c;
        float w00 = fmaxf(acc[nt][0] + sc1[j0],     0.f);
        float w01 = fmaxf(acc[nt][1] + sc1[j0 + 1], 0.f);
        float w10 = fmaxf(acc[nt][2] + sc1[j0],     0.f);
        float w11 = fmaxf(acc[nt][3] + sc1[j0 + 1], 0.f);
        uint2 lo = make_uint2(f2tf32(w00), f2tf32(w01));
        uint2 hi = make_uint2(f2tf32(w10), f2tf32(w11));
        *(uint2*)&sA[(rb + g)     * AP + j0] = lo;
        *(uint2*)&sA[(rb + g + 8) * AP + j0] = hi;
    }
    __syncwarp();

    // ---- GEMM 2 ----
    #pragma unroll
    for (int nt = 0; nt < 8; nt++)
        #pragma unroll
        for (int i = 0; i < 4; i++) acc[nt][i] = 0.f;

    #pragma unroll
    for (int ks = 0; ks < 8; ks++) {
        int k0 = ks * 8;
        uint32_t a0 = sA[(rb + g)     * AP + k0 + c];
        uint32_t a1 = sA[(rb + g + 8) * AP + k0 + c];
        uint32_t a2 = sA[(rb + g)     * AP + k0 + c + 4];
        uint32_t a3 = sA[(rb + g + 8) * AP + k0 + c + 4];
        #pragma unroll
        for (int nt = 0; nt < 8; nt++) {
            uint32_t b0 = sW2[(k0 + c)     * WP + nt * 8 + g];
            uint32_t b1r = sW2[(k0 + c + 4) * WP + nt * 8 + g];
            mma_tf32(acc[nt], a0, a1, a2, a3, b0, b1r);
        }
    }

    // Epilogue 2: ReLU(z + c2), outer BN, optional ReLU, store float2 pairs.
    int r0 = rowbase + rb + g;
    int r1 = r0 + 8;
    #pragma unroll
    for (int nt = 0; nt < 8; nt++) {
        int j0 = nt * 8 + 2 * c;
        float s0 = ssg[j0], s1 = ssg[j0 + 1];
        float t0 = sst[j0], t1 = sst[j0 + 1];
        float2 o0, o1;
        o0.x = s0 * fmaxf(acc[nt][0] + sc2[j0],     0.f) + t0;
        o0.y = s1 * fmaxf(acc[nt][1] + sc2[j0 + 1], 0.f) + t1;
        o1.x = s0 * fmaxf(acc[nt][2] + sc2[j0],     0.f) + t0;
        o1.y = s1 * fmaxf(acc[nt][3] + sc2[j0 + 1], 0.f) + t1;
        if (do_relu) {
            o0.x = fmaxf(o0.x, 0.f); o0.y = fmaxf(o0.y, 0.f);
            o1.x = fmaxf(o1.x, 0.f); o1.y = fmaxf(o1.y, 0.f);
        }
        if (r0 < N_NODES) *(float2*)(out + (size_t)r0 * CC + j0) = o0;
        if (r1 < N_NODES) *(float2*)(out + (size_t)r1 * CC + j0) = o1;
    }
}

extern "C" void kernel_launch(void* const* d_in, const int* in_sizes, int n_in,
                              void* d_out, int out_size) {
    const float* x   = (const float*)d_in[0];
    const int*   ei  = (const int*)d_in[1];
    const float* eps = (const float*)d_in[2];
    const float* W1  = (const float*)d_in[3];
    const float* b1  = (const float*)d_in[4];
    const float* g1  = (const float*)d_in[5];
    const float* be1 = (const float*)d_in[6];
    const float* W2  = (const float*)d_in[7];
    const float* b2  = (const float*)d_in[8];
    const float* g2  = (const float*)d_in[9];
    const float* be2 = (const float*)d_in[10];
    const float* bng = (const float*)d_in[11];
    const float* bnb = (const float*)d_in[12];
    float* out = (float*)d_out;

    float *hb, *xa, *xb;
    int *cnt, *off, *cur, *csr, *bsum;
    cudaGetSymbolAddress((void**)&hb,   g_h);
    cudaGetSymbolAddress((void**)&xa,   g_xa);
    cudaGetSymbolAddress((void**)&xb,   g_xb);
    cudaGetSymbolAddress((void**)&cnt,  g_cnt);
    cudaGetSymbolAddress((void**)&off,  g_off);
    cudaGetSymbolAddress((void**)&cur,  g_cur);
    cudaGetSymbolAddress((void**)&csr,  g_csr);
    cudaGetSymbolAddress((void**)&bsum, g_bsum);

    const int smem_bytes = SF_TOT * 4;  // 72704
    cudaFuncSetAttribute(mlp_tc_kernel,
                         cudaFuncAttributeMaxDynamicSharedMemorySize, smem_bytes);

    const int eblk = (N_EDGES + 255) / 256;
    const int nblk = (N_NODES + 255) / 256;
    const int mlp_blocks = (N_NODES + 127) / 128;       // 782
    const int agg_blocks = (N_NODES * 32 + 255) / 256;  // 12500

    // CSR build (edge_index constant across layers).
    cudaMemsetAsync(cnt, 0, N_NODES * sizeof(int));
    hist_kernel<<<eblk, 256>>>(ei, cnt);
    scan_blocks_kernel<<<N_SCANB, SCAN_BLK>>>(cnt, off, bsum);
    scan_bsum_kernel<<<1, 128>>>(bsum);
    add_off_kernel<<<nblk, 256>>>(off, bsum, cur);
    fill_csr_kernel<<<eblk, 256>>>(ei, cur, csr);

    const float* xin = x;
    float* outs[NL] = {xa, xb, out};
    for (int l = 0; l < NL; l++) {
        agg_kernel<<<agg_blocks, 256>>>(xin, off, cnt, csr, eps, l, hb);
        mlp_tc_kernel<<<mlp_blocks, 256, smem_bytes>>>(
            hb, outs[l],
            W1 + l * 4096, b1 + l * 64, g1 + l * 64, be1 + l * 64,
            W2 + l * 4096, b2 + l * 64, g2 + l * 64, be2 + l * 64,
            bng + l * 64, bnb + l * 64, (l < NL - 1) ? 1 : 0);
        xin = outs[l];
    }
}